// round 4
// baseline (speedup 1.0000x reference)
#include <cuda_runtime.h>
#include <math.h>
#include <stdint.h>

#define N_NODES 100000
#define N_EDGES 1600000
#define FNODE   64
#define FEDGE   32
#define EPSBN   1e-5f

// ---------------- device scratch --------------------------------------------
__device__ __align__(16) float  g_P[(size_t)N_NODES * 128];   // node @ W[0:64,:]   (int|upd)
__device__ __align__(16) float  g_Q[(size_t)N_NODES * 128];   // node @ W[64:128,:] (int|upd)
__device__ __align__(16) float  g_agg[(size_t)N_NODES * FNODE];
__device__ double g_sum[128];
__device__ double g_sumsq[128];
__device__ __align__(16) float  g_escale[128];
__device__ __align__(16) float  g_eshift[128];
__device__ double g_nsum[FNODE];
__device__ double g_nsumsq[FNODE];
__device__ float  g_nscale[FNODE];
__device__ float  g_nshift[FNODE];

// ---------------- helpers ----------------------------------------------------
__device__ __forceinline__ unsigned long long pk2(float x, float y) {
    unsigned long long r;
    asm("mov.b64 %0, {%1, %2};" : "=l"(r) : "f"(x), "f"(y));
    return r;
}
__device__ __forceinline__ void upk2(unsigned long long v, float& x, float& y) {
    asm("mov.b64 {%0, %1}, %2;" : "=f"(x), "=f"(y) : "l"(v));
}
__device__ __forceinline__ void fma2(unsigned long long& acc,
                                     unsigned long long a, unsigned long long b) {
    asm("fma.rn.f32x2 %0, %1, %2, %0;" : "+l"(acc) : "l"(a), "l"(b));
}
__device__ __forceinline__ float sigf(float x) {
    return __fdividef(1.0f, 1.0f + __expf(-x));
}
__device__ __forceinline__ float spf(float x) {
    return fmaxf(x, 0.0f) + __logf(1.0f + __expf(-fabsf(x)));
}
__device__ __forceinline__ void red_add_v4(float* p, float4 v) {
    asm volatile("red.global.add.v4.f32 [%0], {%1, %2, %3, %4};"
                 :: "l"(p), "f"(v.x), "f"(v.y), "f"(v.z), "f"(v.w) : "memory");
}

#define EPW 4   // edges per warp

// Shared edge-GEMM core: computes acc (4 cols per lane) for EPW edges.
// swc[32][128] must hold W rows 128..159 (int cols 0-63 | upd cols 64-127).
#define EDGE_GEMM_BODY(a0, a1, mef, sidx, didx, b4)                              \
    {                                                                            \
        _Pragma("unroll")                                                        \
        for (int i = 0; i < EPW; ++i) {                                          \
            const float4 p = __ldg((const float4*)&g_P[(size_t)sidx[i] * 128 + 4 * lane]); \
            const float4 q = __ldg((const float4*)&g_Q[(size_t)didx[i] * 128 + 4 * lane]); \
            a0[i] = pk2(p.x + q.x + b4.x, p.y + q.y + b4.y);                     \
            a1[i] = pk2(p.z + q.z + b4.z, p.w + q.w + b4.w);                     \
        }                                                                        \
        _Pragma("unroll 8")                                                      \
        for (int k = 0; k < 32; ++k) {                                           \
            const ulonglong2 w = *(const ulonglong2*)&swc[k * 128 + 4 * lane];   \
            _Pragma("unroll")                                                    \
            for (int i = 0; i < EPW; ++i) {                                      \
                const float ev = __shfl_sync(0xffffffffu, mef[i], k);            \
                const unsigned long long e2 = pk2(ev, ev);                       \
                fma2(a0[i], e2, w.x);                                            \
                fma2(a1[i], e2, w.y);                                            \
            }                                                                    \
        }                                                                        \
    }

// ---------------- K1: P/Q node GEMMs -----------------------------------------
__global__ void __launch_bounds__(256)
k1_node_gemm(const float* __restrict__ node,
             const float* __restrict__ Wint,
             const float* __restrict__ Wupd) {
    __shared__ __align__(16) float sn[32 * 64];
    __shared__ __align__(16) float sw[64 * 128];
    const int tid = threadIdx.x;
    const int nbase = blockIdx.x * 32;

    for (int i = tid; i < 32 * 64; i += 256)
        sn[i] = node[(size_t)nbase * 64 + i];

    const int cg = tid & 31;
    const int ng = tid >> 5;

    for (int pass = 0; pass < 2; ++pass) {
        __syncthreads();
        for (int i = tid; i < 64 * 128; i += 256) {
            int k = i >> 7, c = i & 127;
            int krow = pass * 64 + k;
            sw[i] = (c < 64) ? Wint[krow * 64 + c] : Wupd[krow * 64 + (c - 64)];
        }
        __syncthreads();

        float4 acc[4];
#pragma unroll
        for (int i = 0; i < 4; ++i) acc[i] = make_float4(0.f, 0.f, 0.f, 0.f);

#pragma unroll 8
        for (int k = 0; k < 64; ++k) {
            float4 w = *(const float4*)&sw[k * 128 + 4 * cg];
#pragma unroll
            for (int i = 0; i < 4; ++i) {
                float nv = sn[(4 * ng + i) * 64 + k];
                acc[i].x += nv * w.x;
                acc[i].y += nv * w.y;
                acc[i].z += nv * w.z;
                acc[i].w += nv * w.w;
            }
        }
        float* dstp = (pass == 0) ? g_P : g_Q;
#pragma unroll
        for (int i = 0; i < 4; ++i)
            *(float4*)&dstp[(size_t)(nbase + 4 * ng + i) * 128 + 4 * cg] = acc[i];
    }
}

// ---------------- KA: edge stats pass (no spill) ------------------------------
__global__ void __launch_bounds__(256, 3)
kA_stats(const float* __restrict__ ef,
         const int* __restrict__ src,
         const int* __restrict__ dst,
         const float* __restrict__ Wint,
         const float* __restrict__ Wupd,
         const float* __restrict__ bint,
         const float* __restrict__ bupd) {
    __shared__ __align__(16) float swc[32 * 128];
    __shared__ __align__(16) float sb[128];
    __shared__ __align__(16) float sred[8][128];
    __shared__ __align__(16) float sred2[8][128];

    const int tid = threadIdx.x;
    for (int i = tid; i < 32 * 128; i += 256) {
        int k = i >> 7, c = i & 127;
        swc[i] = (c < 64) ? Wint[(128 + k) * 64 + c] : Wupd[(128 + k) * 64 + (c - 64)];
    }
    if (tid < 128) sb[tid] = (tid < 64) ? bint[tid] : bupd[tid - 64];
    __syncthreads();

    const int warp = tid >> 5, lane = tid & 31;
    const size_t ebase = (size_t)blockIdx.x * (8 * EPW) + (size_t)warp * EPW;
    const float4 b4 = *(const float4*)&sb[4 * lane];

    int   sI[EPW], dI[EPW];
    float mef[EPW];
#pragma unroll
    for (int i = 0; i < EPW; ++i) {
        const size_t e = ebase + i;
        sI[i] = src[e];
        dI[i] = dst[e];
        mef[i] = __ldcs(&ef[e * 32 + lane]);   // streaming: evict-first
    }

    unsigned long long a0[EPW], a1[EPW];
    EDGE_GEMM_BODY(a0, a1, mef, sI, dI, b4);

    float4 ls = make_float4(0.f, 0.f, 0.f, 0.f);
    float4 lq = make_float4(0.f, 0.f, 0.f, 0.f);
#pragma unroll
    for (int i = 0; i < EPW; ++i) {
        float x, y, z, w;
        upk2(a0[i], x, y);
        upk2(a1[i], z, w);
        ls.x += x; ls.y += y; ls.z += z; ls.w += w;
        lq.x += x * x; lq.y += y * y; lq.z += z * z; lq.w += w * w;
    }
    *(float4*)&sred[warp][4 * lane]  = ls;
    *(float4*)&sred2[warp][4 * lane] = lq;
    __syncthreads();

    if (tid < 128) {
        float v = 0.f;
#pragma unroll
        for (int w = 0; w < 8; ++w) v += sred[w][tid];
        atomicAdd(&g_sum[tid], (double)v);
    } else {
        const int c = tid - 128;
        float v = 0.f;
#pragma unroll
        for (int w = 0; w < 8; ++w) v += sred2[w][c];
        atomicAdd(&g_sumsq[c], (double)v);
    }
}

// ---------------- K3: finalize edge BN ----------------------------------------
__global__ void k3_edge_bn(const float* __restrict__ gint,
                           const float* __restrict__ beint,
                           const float* __restrict__ gupd,
                           const float* __restrict__ beupd) {
    const int c = threadIdx.x;  // 128
    const double mu  = g_sum[c]   / (double)N_EDGES;
    const double var = g_sumsq[c] / (double)N_EDGES - mu * mu;
    const float gam = (c < 64) ? gint[c] : gupd[c - 64];
    const float bet = (c < 64) ? beint[c] : beupd[c - 64];
    const float sc = gam * rsqrtf((float)var + EPSBN);
    g_escale[c] = sc;
    g_eshift[c] = bet - (float)mu * sc;
}

// ---------------- KB: recompute + BN + act + scatter ---------------------------
__global__ void __launch_bounds__(256, 3)
kB_apply(const float* __restrict__ ef,
         const int* __restrict__ src,
         const int* __restrict__ dst,
         const float* __restrict__ Wint,
         const float* __restrict__ Wupd,
         const float* __restrict__ bint,
         const float* __restrict__ bupd) {
    __shared__ __align__(16) float swc[32 * 128];
    __shared__ __align__(16) float sb[128];

    const int tid = threadIdx.x;
    for (int i = tid; i < 32 * 128; i += 256) {
        int k = i >> 7, c = i & 127;
        swc[i] = (c < 64) ? Wint[(128 + k) * 64 + c] : Wupd[(128 + k) * 64 + (c - 64)];
    }
    if (tid < 128) sb[tid] = (tid < 64) ? bint[tid] : bupd[tid - 64];
    __syncthreads();

    const int warp = tid >> 5, lane = tid & 31;
    const size_t ebase = (size_t)blockIdx.x * (8 * EPW) + (size_t)warp * EPW;
    const float4 b4 = *(const float4*)&sb[4 * lane];
    const float4 sc4 = *(const float4*)&g_escale[4 * lane];
    const float4 sh4 = *(const float4*)&g_eshift[4 * lane];

    int   sI[EPW], dI[EPW];
    float mef[EPW];
#pragma unroll
    for (int i = 0; i < EPW; ++i) {
        const size_t e = ebase + i;
        sI[i] = src[e];
        dI[i] = dst[e];
        mef[i] = __ldcs(&ef[e * 32 + lane]);   // streaming: evict-first
    }

    unsigned long long a0[EPW], a1[EPW];
    EDGE_GEMM_BODY(a0, a1, mef, sI, dI, b4);

#pragma unroll
    for (int i = 0; i < EPW; ++i) {
        float4 v;
        upk2(a0[i], v.x, v.y);
        upk2(a1[i], v.z, v.w);
        float4 z;
        z.x = fmaf(v.x, sc4.x, sh4.x);
        z.y = fmaf(v.y, sc4.y, sh4.y);
        z.z = fmaf(v.z, sc4.z, sh4.z);
        z.w = fmaf(v.w, sc4.w, sh4.w);

        float4 a;
        if (lane < 16) {            // gate columns 0..63
            a.x = sigf(z.x); a.y = sigf(z.y); a.z = sigf(z.z); a.w = sigf(z.w);
        } else {                    // upd columns 64..127
            a.x = spf(z.x);  a.y = spf(z.y);  a.z = spf(z.z);  a.w = spf(z.w);
        }

        float4 m;
        m.x = a.x * __shfl_sync(0xffffffffu, a.x, lane + 16);
        m.y = a.y * __shfl_sync(0xffffffffu, a.y, lane + 16);
        m.z = a.z * __shfl_sync(0xffffffffu, a.z, lane + 16);
        m.w = a.w * __shfl_sync(0xffffffffu, a.w, lane + 16);

        if (lane < 16)
            red_add_v4(&g_agg[(size_t)dI[i] * 64 + 4 * lane], m);
    }
}

// ---------------- K5: node BN stats over agg -----------------------------------
__global__ void __launch_bounds__(256)
k5_node_stats() {
    const int tid = threadIdx.x;
    const int c = tid & 63;
    const int r0 = blockIdx.x * 512 + (tid >> 6);
    const int end = min((blockIdx.x + 1) * 512, N_NODES);

    float s = 0.f, ss = 0.f;
    for (int r = r0; r < end; r += 4) {
        float v = g_agg[(size_t)r * 64 + c];
        s += v;
        ss += v * v;
    }
    __shared__ float red[256], red2[256];
    red[tid] = s;
    red2[tid] = ss;
    __syncthreads();
    if (tid < 64) {
        float a  = red[tid]  + red[tid + 64]  + red[tid + 128]  + red[tid + 192];
        float b2 = red2[tid] + red2[tid + 64] + red2[tid + 128] + red2[tid + 192];
        atomicAdd(&g_nsum[tid], (double)a);
        atomicAdd(&g_nsumsq[tid], (double)b2);
    }
}

__global__ void k5b_node_bn(const float* __restrict__ gbn,
                            const float* __restrict__ bebn) {
    const int c = threadIdx.x;  // 64
    const double mu  = g_nsum[c]   / (double)N_NODES;
    const double var = g_nsumsq[c] / (double)N_NODES - mu * mu;
    const float sc = gbn[c] * rsqrtf((float)var + EPSBN);
    g_nscale[c] = sc;
    g_nshift[c] = bebn[c] - (float)mu * sc;
}

// ---------------- K6: final output ----------------------------------------------
__global__ void __launch_bounds__(256)
k6_out(const float* __restrict__ node, float* __restrict__ out) {
    const size_t i = (size_t)blockIdx.x * 256 + threadIdx.x;
    if (i >= (size_t)N_NODES * 64) return;
    const int c = (int)(i & 63);
    const float x = node[i] + g_agg[i] * g_nscale[c] + g_nshift[c];
    out[i] = fmaxf(x, 0.f) + log1pf(expf(-fabsf(x)));
}

// ---------------- launch ---------------------------------------------------------
extern "C" void kernel_launch(void* const* d_in, const int* in_sizes, int n_in,
                              void* d_out, int out_size) {
    const float* node  = (const float*)d_in[0];
    const float* edge  = (const float*)d_in[1];
    const int*   src   = (const int*)d_in[2];
    const int*   dst   = (const int*)d_in[3];
    const float* Wint  = (const float*)d_in[4];
    const float* bint  = (const float*)d_in[5];
    const float* gint  = (const float*)d_in[6];
    const float* beint = (const float*)d_in[7];
    const float* Wupd  = (const float*)d_in[8];
    const float* bupd  = (const float*)d_in[9];
    const float* gupd  = (const float*)d_in[10];
    const float* beupd = (const float*)d_in[11];
    const float* gbn   = (const float*)d_in[12];
    const float* bebn  = (const float*)d_in[13];
    float* out = (float*)d_out;

    void *pSum, *pSumsq, *pNsum, *pNsumsq, *pAgg;
    cudaGetSymbolAddress(&pSum,    g_sum);
    cudaGetSymbolAddress(&pSumsq,  g_sumsq);
    cudaGetSymbolAddress(&pNsum,   g_nsum);
    cudaGetSymbolAddress(&pNsumsq, g_nsumsq);
    cudaGetSymbolAddress(&pAgg,    g_agg);

    cudaMemsetAsync(pSum,    0, 128 * sizeof(double));
    cudaMemsetAsync(pSumsq,  0, 128 * sizeof(double));
    cudaMemsetAsync(pNsum,   0, FNODE * sizeof(double));
    cudaMemsetAsync(pNsumsq, 0, FNODE * sizeof(double));
    cudaMemsetAsync(pAgg,    0, (size_t)N_NODES * FNODE * sizeof(float));

    k1_node_gemm<<<N_NODES / 32, 256>>>(node, Wint, Wupd);
    kA_stats<<<N_EDGES / (8 * EPW), 256>>>(edge, src, dst, Wint, Wupd, bint, bupd);
    k3_edge_bn<<<1, 128>>>(gint, beint, gupd, beupd);
    kB_apply<<<N_EDGES / (8 * EPW), 256>>>(edge, src, dst, Wint, Wupd, bint, bupd);
    k5_node_stats<<<(N_NODES + 511) / 512, 256>>>();
    k5b_node_bn<<<1, 64>>>(gbn, bebn);
    k6_out<<<((size_t)N_NODES * 64 + 255) / 256, 256>>>(node, out);
}

// round 5
// speedup vs baseline: 1.9046x; 1.9046x over previous
#include <cuda_runtime.h>
#include <cuda_fp16.h>
#include <math.h>
#include <stdint.h>

#define N_NODES 100000
#define N_EDGES 1600000
#define FNODE   64
#define FEDGE   32
#define EPSBN   1e-5f

// ---------------- device scratch --------------------------------------------
__device__ __align__(16) float  g_P[(size_t)N_NODES * 128];   // node @ W[0:64,:]   (int|upd)
__device__ __align__(16) float  g_Q[(size_t)N_NODES * 128];   // node @ W[64:128,:] (int|upd)
__device__ __align__(16) __half g_Yh[(size_t)N_EDGES * 128];  // pre-BN edge outputs, fp16
__device__ __align__(16) float  g_agg[(size_t)N_NODES * FNODE];
__device__ double g_sum[128];
__device__ double g_sumsq[128];
__device__ __align__(16) float  g_escale[128];
__device__ __align__(16) float  g_eshift[128];
__device__ double g_nsum[FNODE];
__device__ double g_nsumsq[FNODE];
__device__ float  g_nscale[FNODE];
__device__ float  g_nshift[FNODE];

// ---------------- helpers ----------------------------------------------------
__device__ __forceinline__ unsigned long long pk2(float x, float y) {
    unsigned long long r;
    asm("mov.b64 %0, {%1, %2};" : "=l"(r) : "f"(x), "f"(y));
    return r;
}
__device__ __forceinline__ void upk2(unsigned long long v, float& x, float& y) {
    asm("mov.b64 {%0, %1}, %2;" : "=f"(x), "=f"(y) : "l"(v));
}
__device__ __forceinline__ void fma2(unsigned long long& acc,
                                     unsigned long long a, unsigned long long b) {
    asm("fma.rn.f32x2 %0, %1, %2, %0;" : "+l"(acc) : "l"(a), "l"(b));
}
__device__ __forceinline__ float sigf(float x) {
    return __fdividef(1.0f, 1.0f + __expf(-x));
}
__device__ __forceinline__ float spf(float x) {
    return fmaxf(x, 0.0f) + __logf(1.0f + __expf(-fabsf(x)));
}
__device__ __forceinline__ void red_add_v4(float* p, float4 v) {
    asm volatile("red.global.add.v4.f32 [%0], {%1, %2, %3, %4};"
                 :: "l"(p), "f"(v.x), "f"(v.y), "f"(v.z), "f"(v.w) : "memory");
}

#define EPW 8   // edges per warp

// ---------------- K1: P/Q node GEMMs -----------------------------------------
__global__ void __launch_bounds__(256)
k1_node_gemm(const float* __restrict__ node,
             const float* __restrict__ Wint,
             const float* __restrict__ Wupd) {
    __shared__ __align__(16) float sn[32 * 64];
    __shared__ __align__(16) float sw[64 * 128];
    const int tid = threadIdx.x;
    const int nbase = blockIdx.x * 32;

    for (int i = tid; i < 32 * 64; i += 256)
        sn[i] = node[(size_t)nbase * 64 + i];

    const int cg = tid & 31;
    const int ng = tid >> 5;

    for (int pass = 0; pass < 2; ++pass) {
        __syncthreads();
        for (int i = tid; i < 64 * 128; i += 256) {
            int k = i >> 7, c = i & 127;
            int krow = pass * 64 + k;
            sw[i] = (c < 64) ? Wint[krow * 64 + c] : Wupd[krow * 64 + (c - 64)];
        }
        __syncthreads();

        float4 acc[4];
#pragma unroll
        for (int i = 0; i < 4; ++i) acc[i] = make_float4(0.f, 0.f, 0.f, 0.f);

#pragma unroll 8
        for (int k = 0; k < 64; ++k) {
            float4 w = *(const float4*)&sw[k * 128 + 4 * cg];
#pragma unroll
            for (int i = 0; i < 4; ++i) {
                float nv = sn[(4 * ng + i) * 64 + k];
                acc[i].x += nv * w.x;
                acc[i].y += nv * w.y;
                acc[i].z += nv * w.z;
                acc[i].w += nv * w.w;
            }
        }
        float* dstp = (pass == 0) ? g_P : g_Q;
#pragma unroll
        for (int i = 0; i < 4; ++i)
            *(float4*)&dstp[(size_t)(nbase + 4 * ng + i) * 128 + 4 * cg] = acc[i];
    }
}

// ---------------- KA: edge GEMM + fp16 spill + stats --------------------------
// 8 warps x 8 edges per block. Lane owns 4 output cols.
// ef staged in smem pre-packed as (v,v) 8-byte pairs -> broadcast LDS in k-loop.
__global__ void __launch_bounds__(256, 2)
kA_edge(const float* __restrict__ ef,
        const int* __restrict__ src,
        const int* __restrict__ dst,
        const float* __restrict__ Wint,
        const float* __restrict__ Wupd,
        const float* __restrict__ bint,
        const float* __restrict__ bupd) {
    __shared__ __align__(16) float swc[32 * 128];          // 16 KB weights
    __shared__ __align__(16) unsigned long long sef[8 * 8 * 32];  // 16 KB staged ef
    __shared__ __align__(16) float sb[128];
    __shared__ __align__(16) float sred[8][128];
    __shared__ __align__(16) float sred2[8][128];

    const int tid = threadIdx.x;
    for (int i = tid; i < 32 * 128; i += 256) {
        int k = i >> 7, c = i & 127;
        swc[i] = (c < 64) ? Wint[(128 + k) * 64 + c] : Wupd[(128 + k) * 64 + (c - 64)];
    }
    if (tid < 128) sb[tid] = (tid < 64) ? bint[tid] : bupd[tid - 64];
    __syncthreads();

    const int warp = tid >> 5, lane = tid & 31;
    const size_t ebase = (size_t)blockIdx.x * (8 * EPW) + (size_t)warp * EPW;
    const float4 b4 = *(const float4*)&sb[4 * lane];
    unsigned long long* sefp = &sef[warp * (EPW * 32)];

    // stage ef pre-packed: lane = feature index k
#pragma unroll
    for (int i = 0; i < EPW; ++i) {
        const float v = __ldcs(&ef[(ebase + i) * 32 + lane]);
        sefp[i * 32 + lane] = pk2(v, v);
    }
    __syncwarp();

    int sI[EPW], dI[EPW];
#pragma unroll
    for (int i = 0; i < EPW; ++i) {
        sI[i] = src[ebase + i];
        dI[i] = dst[ebase + i];
    }

    unsigned long long a0[EPW], a1[EPW];
#pragma unroll
    for (int i = 0; i < EPW; ++i) {
        const float4 p = __ldg((const float4*)&g_P[(size_t)sI[i] * 128 + 4 * lane]);
        const float4 q = __ldg((const float4*)&g_Q[(size_t)dI[i] * 128 + 4 * lane]);
        a0[i] = pk2(p.x + q.x + b4.x, p.y + q.y + b4.y);
        a1[i] = pk2(p.z + q.z + b4.z, p.w + q.w + b4.w);
    }

#pragma unroll
    for (int kk = 0; kk < 32; kk += 2) {
        const ulonglong2 w0 = *(const ulonglong2*)&swc[kk * 128 + 4 * lane];
        const ulonglong2 w1 = *(const ulonglong2*)&swc[(kk + 1) * 128 + 4 * lane];
#pragma unroll
        for (int i = 0; i < EPW; ++i) {
            const ulonglong2 e2 = *(const ulonglong2*)&sefp[i * 32 + kk];
            fma2(a0[i], e2.x, w0.x);
            fma2(a1[i], e2.x, w0.y);
            fma2(a0[i], e2.y, w1.x);
            fma2(a1[i], e2.y, w1.y);
        }
    }

    // spill fp16 Y + accumulate fp32 stats
    float4 ls = make_float4(0.f, 0.f, 0.f, 0.f);
    float4 lq = make_float4(0.f, 0.f, 0.f, 0.f);
#pragma unroll
    for (int i = 0; i < EPW; ++i) {
        float x, y, z, w;
        upk2(a0[i], x, y);
        upk2(a1[i], z, w);
        __half2 h01 = __floats2half2_rn(x, y);
        __half2 h23 = __floats2half2_rn(z, w);
        uint2 hv = make_uint2(*(unsigned*)&h01, *(unsigned*)&h23);
        __stcs((uint2*)&g_Yh[(ebase + i) * 128 + 4 * lane], hv);
        ls.x += x; ls.y += y; ls.z += z; ls.w += w;
        lq.x += x * x; lq.y += y * y; lq.z += z * z; lq.w += w * w;
    }
    *(float4*)&sred[warp][4 * lane]  = ls;
    *(float4*)&sred2[warp][4 * lane] = lq;
    __syncthreads();

    if (tid < 128) {
        float v = 0.f;
#pragma unroll
        for (int w = 0; w < 8; ++w) v += sred[w][tid];
        atomicAdd(&g_sum[tid], (double)v);
    } else {
        const int c = tid - 128;
        float v = 0.f;
#pragma unroll
        for (int w = 0; w < 8; ++w) v += sred2[w][c];
        atomicAdd(&g_sumsq[c], (double)v);
    }
}

// ---------------- K3: finalize edge BN ----------------------------------------
__global__ void k3_edge_bn(const float* __restrict__ gint,
                           const float* __restrict__ beint,
                           const float* __restrict__ gupd,
                           const float* __restrict__ beupd) {
    const int c = threadIdx.x;  // 128
    const double mu  = g_sum[c]   / (double)N_EDGES;
    const double var = g_sumsq[c] / (double)N_EDGES - mu * mu;
    const float gam = (c < 64) ? gint[c] : gupd[c - 64];
    const float bet = (c < 64) ? beint[c] : beupd[c - 64];
    const float sc = gam * rsqrtf((float)var + EPSBN);
    g_escale[c] = sc;
    g_eshift[c] = bet - (float)mu * sc;
}

// ---------------- KB: stream Yh, BN + act + scatter ----------------------------
// warp = 2 edges; lane s = lane&15 owns 4 cols; gate+upd both in-lane (no shfl).
__global__ void __launch_bounds__(256)
kB_apply(const int* __restrict__ dst) {
    const int tid = threadIdx.x;
    const int warp = tid >> 5, lane = tid & 31;
    const int s = lane & 15;
    const size_t e = (size_t)blockIdx.x * 16 + (size_t)warp * 2 + (lane >> 4);

    const uint2 gv = __ldcs((const uint2*)&g_Yh[e * 128 + 4 * s]);
    const uint2 uv = __ldcs((const uint2*)&g_Yh[e * 128 + 64 + 4 * s]);

    const float2 g01 = __half22float2(*(const __half2*)&gv.x);
    const float2 g23 = __half22float2(*(const __half2*)&gv.y);
    const float2 u01 = __half22float2(*(const __half2*)&uv.x);
    const float2 u23 = __half22float2(*(const __half2*)&uv.y);

    const float4 gs = *(const float4*)&g_escale[4 * s];
    const float4 gh = *(const float4*)&g_eshift[4 * s];
    const float4 us = *(const float4*)&g_escale[64 + 4 * s];
    const float4 uh = *(const float4*)&g_eshift[64 + 4 * s];

    float4 m;
    m.x = sigf(fmaf(g01.x, gs.x, gh.x)) * spf(fmaf(u01.x, us.x, uh.x));
    m.y = sigf(fmaf(g01.y, gs.y, gh.y)) * spf(fmaf(u01.y, us.y, uh.y));
    m.z = sigf(fmaf(g23.x, gs.z, gh.z)) * spf(fmaf(u23.x, us.z, uh.z));
    m.w = sigf(fmaf(g23.y, gs.w, gh.w)) * spf(fmaf(u23.y, us.w, uh.w));

    const int d = dst[e];
    red_add_v4(&g_agg[(size_t)d * 64 + 4 * s], m);
}

// ---------------- K5: node BN stats over agg -----------------------------------
__global__ void __launch_bounds__(256)
k5_node_stats() {
    const int tid = threadIdx.x;
    const int c = tid & 63;
    const int r0 = blockIdx.x * 512 + (tid >> 6);
    const int end = min((blockIdx.x + 1) * 512, N_NODES);

    float s = 0.f, ss = 0.f;
    for (int r = r0; r < end; r += 4) {
        float v = g_agg[(size_t)r * 64 + c];
        s += v;
        ss += v * v;
    }
    __shared__ float red[256], red2[256];
    red[tid] = s;
    red2[tid] = ss;
    __syncthreads();
    if (tid < 64) {
        float a  = red[tid]  + red[tid + 64]  + red[tid + 128]  + red[tid + 192];
        float b2 = red2[tid] + red2[tid + 64] + red2[tid + 128] + red2[tid + 192];
        atomicAdd(&g_nsum[tid], (double)a);
        atomicAdd(&g_nsumsq[tid], (double)b2);
    }
}

__global__ void k5b_node_bn(const float* __restrict__ gbn,
                            const float* __restrict__ bebn) {
    const int c = threadIdx.x;  // 64
    const double mu  = g_nsum[c]   / (double)N_NODES;
    const double var = g_nsumsq[c] / (double)N_NODES - mu * mu;
    const float sc = gbn[c] * rsqrtf((float)var + EPSBN);
    g_nscale[c] = sc;
    g_nshift[c] = bebn[c] - (float)mu * sc;
}

// ---------------- K6: final output ----------------------------------------------
__global__ void __launch_bounds__(256)
k6_out(const float* __restrict__ node, float* __restrict__ out) {
    const size_t i = (size_t)blockIdx.x * 256 + threadIdx.x;
    if (i >= (size_t)N_NODES * 64) return;
    const int c = (int)(i & 63);
    const float x = node[i] + g_agg[i] * g_nscale[c] + g_nshift[c];
    out[i] = fmaxf(x, 0.f) + log1pf(expf(-fabsf(x)));
}

// ---------------- launch ---------------------------------------------------------
extern "C" void kernel_launch(void* const* d_in, const int* in_sizes, int n_in,
                              void* d_out, int out_size) {
    const float* node  = (const float*)d_in[0];
    const float* edge  = (const float*)d_in[1];
    const int*   src   = (const int*)d_in[2];
    const int*   dst   = (const int*)d_in[3];
    const float* Wint  = (const float*)d_in[4];
    const float* bint  = (const float*)d_in[5];
    const float* gint  = (const float*)d_in[6];
    const float* beint = (const float*)d_in[7];
    const float* Wupd  = (const float*)d_in[8];
    const float* bupd  = (const float*)d_in[9];
    const float* gupd  = (const float*)d_in[10];
    const float* beupd = (const float*)d_in[11];
    const float* gbn   = (const float*)d_in[12];
    const float* bebn  = (const float*)d_in[13];
    float* out = (float*)d_out;

    void *pSum, *pSumsq, *pNsum, *pNsumsq, *pAgg;
    cudaGetSymbolAddress(&pSum,    g_sum);
    cudaGetSymbolAddress(&pSumsq,  g_sumsq);
    cudaGetSymbolAddress(&pNsum,   g_nsum);
    cudaGetSymbolAddress(&pNsumsq, g_nsumsq);
    cudaGetSymbolAddress(&pAgg,    g_agg);

    cudaMemsetAsync(pSum,    0, 128 * sizeof(double));
    cudaMemsetAsync(pSumsq,  0, 128 * sizeof(double));
    cudaMemsetAsync(pNsum,   0, FNODE * sizeof(double));
    cudaMemsetAsync(pNsumsq, 0, FNODE * sizeof(double));
    cudaMemsetAsync(pAgg,    0, (size_t)N_NODES * FNODE * sizeof(float));

    k1_node_gemm<<<N_NODES / 32, 256>>>(node, Wint, Wupd);
    kA_edge<<<N_EDGES / (8 * EPW), 256>>>(edge, src, dst, Wint, Wupd, bint, bupd);
    k3_edge_bn<<<1, 128>>>(gint, beint, gupd, beupd);
    kB_apply<<<N_EDGES / 16, 256>>>(dst);
    k5_node_stats<<<(N_NODES + 511) / 512, 256>>>();
    k5b_node_bn<<<1, 64>>>(gbn, bebn);
    k6_out<<<((size_t)N_NODES * 64 + 255) / 256, 256>>>(node, out);
}